// round 5
// baseline (speedup 1.0000x reference)
#include <cuda_runtime.h>
#include <cstdint>

// ---------------------------------------------------------------------------
// LightGCN encoder. Identity: propagation S is linear over features and W
// acts on the feature dim, so  mean_k(S^k x) @ W = mean_k(S^k (x @ W)).
// Pipeline:
//   1. CSR build (edges bucketed by dst), edge weight dis[src]*dis[dst].
//   2. y0 = x @ (0.25*W)              [100k x 64]  (0.25 = mean folded in)
//   3. y1 = S y0, y2 = S y1           (gathers in d=64, L2-resident)
//   4. out = y0+y1+y2+S y2 + b        (fused into layer 3)
// edge_index dtype (int32 vs int64) detected on-device.
// ---------------------------------------------------------------------------

#define NMAX 100000
#define EMAX 625024
#define DFEAT 128
#define DH 64
#define NBMAX 512   // >= ceil(NMAX/256)

__device__ int   g_is64;
__device__ int   g_deg[NMAX];
__device__ float g_dis[NMAX];
__device__ int   g_partial[NBMAX];
__device__ int   g_partofs[NBMAX];
__device__ int   g_rowstart[NMAX + 1];
__device__ int   g_cursor[NMAX];
__device__ int2  g_edge[EMAX];          // {src, bitcast(weight)}
__device__ __align__(16) float g_y0[(size_t)NMAX * DH];
__device__ __align__(16) float g_y1[(size_t)NMAX * DH];
__device__ __align__(16) float g_y2[(size_t)NMAX * DH];

// ---------------------------------------------------------------------------
// Fused: zero degree array + dtype probe (block 0).
__global__ void k_init(const long long* __restrict__ ei, int n) {
    int i = blockIdx.x * blockDim.x + threadIdx.x;
    if (i < n) g_deg[i] = 0;
    if (blockIdx.x == 0) {
        long long v = ei[threadIdx.x];
        int bad = (v < 0 || v >= (long long)n) ? 1 : 0;
        int any = __syncthreads_or(bad);
        if (threadIdx.x == 0) g_is64 = !any;
    }
}

__global__ void k_deg(const void* __restrict__ eiv, int e) {
    int i = blockIdx.x * blockDim.x + threadIdx.x;
    if (i >= e) return;
    int d;
    if (g_is64) d = (int)((const long long*)eiv)[(size_t)e + i];
    else        d = ((const int*)eiv)[(size_t)e + i];
    atomicAdd(&g_deg[d], 1);
}

// block partial sums of deg (+ dis on the way)
__global__ void k_blocksum(int n) {
    __shared__ int s[256];
    int t = threadIdx.x;
    int i = blockIdx.x * 256 + t;
    int v = (i < n) ? g_deg[i] : 0;
    if (i < n) g_dis[i] = (v > 0) ? rsqrtf((float)v) : 0.0f;
    s[t] = v;
    __syncthreads();
    for (int o = 128; o > 0; o >>= 1) {
        if (t < o) s[t] += s[t + o];
        __syncthreads();
    }
    if (t == 0) g_partial[blockIdx.x] = s[0];
}

// y0 = x @ (0.25*W).  BM=128, BN=64(full), BK=32, 256 threads.
// 8x4 micro-tile per thread; A-tile stride 132 floats (528B = 16*33) keeps
// every As[kk][ty*8] fragment 16B-aligned -> LDS.128 on both operands.
__global__ void k_gemm_y(const float* __restrict__ x,
                         const float* __restrict__ W,
                         float* __restrict__ y0, int n) {
    __shared__ float As[32][132];   // [k][row], padded for .128 alignment
    __shared__ float Bs[32][64];    // [k][col]

    int tid = threadIdx.x;
    int row0 = blockIdx.x * 128;
    int ty = tid >> 4;              // 0..15 -> rows ty*8..ty*8+7
    int tx = tid & 15;              // 0..15 -> cols tx*4..tx*4+3

    float c[8][4];
    #pragma unroll
    for (int i = 0; i < 8; i++)
        #pragma unroll
        for (int j = 0; j < 4; j++) c[i][j] = 0.f;

    for (int k0 = 0; k0 < DFEAT; k0 += 32) {
        // A: 128 rows x 32 k, float4 loads, transposed store
        #pragma unroll
        for (int j = 0; j < 4; j++) {
            int idx = tid + j * 256;        // 0..1023
            int r  = idx >> 3;              // 0..127
            int k4 = (idx & 7) * 4;         // 0,4,..,28
            float4 v = make_float4(0.f, 0.f, 0.f, 0.f);
            int row = row0 + r;
            if (row < n) v = *(const float4*)(x + (size_t)row * DFEAT + k0 + k4);
            As[k4 + 0][r] = v.x; As[k4 + 1][r] = v.y;
            As[k4 + 2][r] = v.z; As[k4 + 3][r] = v.w;
        }
        // B: 32 k x 64 cols, float4, *0.25 folded
        #pragma unroll
        for (int j = 0; j < 2; j++) {
            int idx = tid + j * 256;        // 0..511
            int kk = idx >> 4;
            int c4 = (idx & 15) * 4;
            float4 v = *(const float4*)(W + (size_t)(k0 + kk) * DH + c4);
            Bs[kk][c4 + 0] = 0.25f * v.x; Bs[kk][c4 + 1] = 0.25f * v.y;
            Bs[kk][c4 + 2] = 0.25f * v.z; Bs[kk][c4 + 3] = 0.25f * v.w;
        }
        __syncthreads();

        #pragma unroll
        for (int kk = 0; kk < 32; kk++) {
            float4 a0 = *(const float4*)&As[kk][ty * 8];
            float4 a1 = *(const float4*)&As[kk][ty * 8 + 4];
            float4 bb = *(const float4*)&Bs[kk][tx * 4];
            float a[8] = {a0.x, a0.y, a0.z, a0.w, a1.x, a1.y, a1.z, a1.w};
            float bv[4] = {bb.x, bb.y, bb.z, bb.w};
            #pragma unroll
            for (int i = 0; i < 8; i++)
                #pragma unroll
                for (int j = 0; j < 4; j++)
                    c[i][j] += a[i] * bv[j];
        }
        __syncthreads();
    }

    #pragma unroll
    for (int i = 0; i < 8; i++) {
        int row = row0 + ty * 8 + i;
        if (row < n)
            *(float4*)(y0 + (size_t)row * DH + tx * 4) =
                make_float4(c[i][0], c[i][1], c[i][2], c[i][3]);
    }
}

// scan block partials (one block)
__global__ void k_scanpart(int nb, int n, int e) {
    __shared__ int s[NBMAX];
    int t = threadIdx.x;
    int v = (t < nb) ? g_partial[t] : 0;
    s[t] = v;
    __syncthreads();
    for (int o = 1; o < NBMAX; o <<= 1) {
        int u = 0;
        if (t >= o) u = s[t - o];
        __syncthreads();
        if (t >= o) s[t] += u;
        __syncthreads();
    }
    if (t < nb) g_partofs[t] = s[t] - v;
    if (t == 0) g_rowstart[n] = e;
}

// per-block exclusive rescan -> rowstart/cursor
__global__ void k_rowstart(int n) {
    __shared__ int s[256];
    int t = threadIdx.x;
    int i = blockIdx.x * 256 + t;
    int v = (i < n) ? g_deg[i] : 0;
    s[t] = v;
    __syncthreads();
    for (int o = 1; o < 256; o <<= 1) {
        int u = 0;
        if (t >= o) u = s[t - o];
        __syncthreads();
        if (t >= o) s[t] += u;
        __syncthreads();
    }
    if (i < n) {
        int r = g_partofs[blockIdx.x] + s[t] - v;
        g_rowstart[i] = r;
        g_cursor[i]   = r;
    }
}

__global__ void k_fill(const void* __restrict__ eiv, int e) {
    int i = blockIdx.x * blockDim.x + threadIdx.x;
    if (i >= e) return;
    int s, d;
    if (g_is64) {
        s = (int)((const long long*)eiv)[i];
        d = (int)((const long long*)eiv)[(size_t)e + i];
    } else {
        s = ((const int*)eiv)[i];
        d = ((const int*)eiv)[(size_t)e + i];
    }
    int p = atomicAdd(&g_cursor[d], 1);
    g_edge[p] = make_int2(s, __float_as_int(g_dis[s] * g_dis[d]));
}

// One warp per node in d=64; each lane owns 2 features (float2).
// 8 gathers in flight. LAST=1 fuses: out = y0 + y1 + yin + acc + b.
template <int LAST>
__global__ void k_layer(const float* __restrict__ yin,
                        float* __restrict__ yout,
                        const float* __restrict__ y0,
                        const float* __restrict__ y1,
                        const float* __restrict__ bvec,
                        float* __restrict__ out, int n) {
    int gw = (blockIdx.x * blockDim.x + threadIdx.x) >> 5;
    if (gw >= n) return;
    int lane = threadIdx.x & 31;

    int beg = g_rowstart[gw];
    int end = g_rowstart[gw + 1];
    int last = end - 1;

    float accx = 0.f, accy = 0.f;
    for (int e = beg; e < end; e += 8) {
        int2  p[8];
        float w[8];
        #pragma unroll
        for (int j = 0; j < 8; j++) {
            p[j] = g_edge[min(e + j, last)];
            w[j] = (e + j <= last) ? __int_as_float(p[j].y) : 0.f;
        }
        float2 v[8];
        #pragma unroll
        for (int j = 0; j < 8; j++)
            v[j] = *(const float2*)(yin + (size_t)p[j].x * DH + lane * 2);
        #pragma unroll
        for (int j = 0; j < 8; j++) {
            accx += w[j] * v[j].x;
            accy += w[j] * v[j].y;
        }
    }

    size_t off = (size_t)gw * DH + lane * 2;
    if (LAST) {
        float2 a = *(const float2*)(y0 + off);
        float2 b = *(const float2*)(y1 + off);
        float2 c = *(const float2*)(yin + off);
        float2 bb = *(const float2*)(bvec + lane * 2);
        float2 o = make_float2(a.x + b.x + c.x + accx + bb.x,
                               a.y + b.y + c.y + accy + bb.y);
        *(float2*)(out + off) = o;
    } else {
        *(float2*)(yout + off) = make_float2(accx, accy);
    }
}

// ---------------------------------------------------------------------------

extern "C" void kernel_launch(void* const* d_in, const int* in_sizes, int n_in,
                              void* d_out, int out_size) {
    const float* x  = (const float*)d_in[0];   // [N,128]
    const float* W  = (const float*)d_in[1];   // [128,64]
    const float* b  = (const float*)d_in[2];   // [64]
    const void*  ei = d_in[3];                 // [2,E]
    float* out = (float*)d_out;

    int n = in_sizes[0] / DFEAT;
    int e = in_sizes[3] / 2;

    float *y0, *y1, *y2;
    cudaGetSymbolAddress((void**)&y0, g_y0);
    cudaGetSymbolAddress((void**)&y1, g_y1);
    cudaGetSymbolAddress((void**)&y2, g_y2);

    const int TB = 256;
    int nb_n = (n + TB - 1) / TB;
    int nb_e = (e + TB - 1) / TB;

    k_init<<<nb_n, TB>>>((const long long*)ei, n);    // 1
    k_deg<<<nb_e, TB>>>(ei, e);                       // 2
    k_blocksum<<<nb_n, TB>>>(n);                      // 3
    k_gemm_y<<<(n + 127) / 128, 256>>>(x, W, y0, n);  // 4  (profiled by ncu)
    k_scanpart<<<1, NBMAX>>>(nb_n, n, e);             // 5
    k_rowstart<<<nb_n, TB>>>(n);                      // 6
    k_fill<<<nb_e, TB>>>(ei, e);                      // 7

    int lg = (n * 32 + TB - 1) / TB;
    k_layer<0><<<lg, TB>>>(y0, y1, nullptr, nullptr, nullptr, nullptr, n); // 8
    k_layer<0><<<lg, TB>>>(y1, y2, nullptr, nullptr, nullptr, nullptr, n); // 9
    k_layer<1><<<lg, TB>>>(y2, nullptr, y0, y1, b, out, n);                // 10
}

// round 6
// speedup vs baseline: 1.1713x; 1.1713x over previous
#include <cuda_runtime.h>
#include <cstdint>

// ---------------------------------------------------------------------------
// LightGCN encoder. Identity: propagation S is linear over features and W
// acts on the feature dim, so  mean_k(S^k x) @ W = mean_k(S^k (x @ W)).
// Pipeline:
//   1. CSR build (edges bucketed by dst), edge weight dis[src]*dis[dst].
//   2. y0 = x @ (0.25*W)   via tf32 tensor-core mma, fp32 accumulate
//   3. y1 = S y0, y2 = S y1           (gathers in d=64, L2-resident)
//   4. out = y0+y1+y2+S y2 + b        (fused into layer 3)
// edge_index dtype (int32 vs int64) detected on-device.
// ---------------------------------------------------------------------------

#define NMAX 100000
#define EMAX 625024
#define DFEAT 128
#define DH 64
#define NBMAX 512   // >= ceil(NMAX/256)

#define AS_STRIDE 132   // 132%32==4 -> A-fragment LDS conflict-free
#define BS_STRIDE 72    // 72%32==8  -> B-fragment LDS conflict-free
#define GEMM_SMEM ((128 * AS_STRIDE + 128 * BS_STRIDE) * 4)

__device__ int   g_is64;
__device__ int   g_deg[NMAX];
__device__ float g_dis[NMAX];
__device__ int   g_partial[NBMAX];
__device__ int   g_partofs[NBMAX];
__device__ int   g_rowstart[NMAX + 1];
__device__ int   g_cursor[NMAX];
__device__ int2  g_edge[EMAX];          // {src, bitcast(weight)}
__device__ __align__(16) float g_y0[(size_t)NMAX * DH];
__device__ __align__(16) float g_y1[(size_t)NMAX * DH];
__device__ __align__(16) float g_y2[(size_t)NMAX * DH];

// ---------------------------------------------------------------------------
// Fused: zero degree array + dtype probe (block 0).
__global__ void k_init(const long long* __restrict__ ei, int n) {
    int i = blockIdx.x * blockDim.x + threadIdx.x;
    if (i < n) g_deg[i] = 0;
    if (blockIdx.x == 0) {
        long long v = ei[threadIdx.x];
        int bad = (v < 0 || v >= (long long)n) ? 1 : 0;
        int any = __syncthreads_or(bad);
        if (threadIdx.x == 0) g_is64 = !any;
    }
}

__global__ void k_deg(const void* __restrict__ eiv, int e) {
    int i = blockIdx.x * blockDim.x + threadIdx.x;
    if (i >= e) return;
    int d;
    if (g_is64) d = (int)((const long long*)eiv)[(size_t)e + i];
    else        d = ((const int*)eiv)[(size_t)e + i];
    atomicAdd(&g_deg[d], 1);
}

// block partial sums of deg (+ dis on the way)
__global__ void k_blocksum(int n) {
    __shared__ int s[256];
    int t = threadIdx.x;
    int i = blockIdx.x * 256 + t;
    int v = (i < n) ? g_deg[i] : 0;
    if (i < n) g_dis[i] = (v > 0) ? rsqrtf((float)v) : 0.0f;
    s[t] = v;
    __syncthreads();
    for (int o = 128; o > 0; o >>= 1) {
        if (t < o) s[t] += s[t + o];
        __syncthreads();
    }
    if (t == 0) g_partial[blockIdx.x] = s[0];
}

__device__ __forceinline__ uint32_t f2tf32(float f) {
    uint32_t u;
    asm("cvt.rna.tf32.f32 %0, %1;" : "=r"(u) : "f"(f));
    return u;
}

// y0 = x @ (0.25*W) via tf32 mma.sync. BM=128, BN=64, full K=128 in smem.
// 256 threads = 8 warps: 4 along M (32 rows each) x 2 along N (32 cols each);
// each warp: 2 m16-tiles x 4 n8-tiles x 16 k8-steps of m16n8k8.
__global__ void k_gemm_y(const float* __restrict__ x,
                         const float* __restrict__ W,
                         float* __restrict__ y0, int n) {
    extern __shared__ float sm[];
    float* As = sm;                      // [128][AS_STRIDE]
    float* Bs = sm + 128 * AS_STRIDE;    // [128][BS_STRIDE]

    int tid = threadIdx.x;
    int row0 = blockIdx.x * 128;

    // A tile: 128 rows x 128 k, float4 coalesced, cvt->tf32 at store
    #pragma unroll
    for (int j = 0; j < 16; j++) {
        int idx = tid + j * 256;          // 0..4095
        int r = idx >> 5;                 // row 0..127
        int q = idx & 31;                 // float4 within row
        float4 v = make_float4(0.f, 0.f, 0.f, 0.f);
        int row = row0 + r;
        if (row < n) v = *(const float4*)(x + (size_t)row * DFEAT + q * 4);
        uint4 t;
        t.x = f2tf32(v.x); t.y = f2tf32(v.y);
        t.z = f2tf32(v.z); t.w = f2tf32(v.w);
        *(uint4*)(As + r * AS_STRIDE + q * 4) = t;
    }
    // B tile: 128 k x 64 n, *0.25 folded, cvt->tf32
    #pragma unroll
    for (int j = 0; j < 8; j++) {
        int idx = tid + j * 256;          // 0..2047
        int r = idx >> 4;                 // k 0..127
        int q = idx & 15;                 // float4 within 64-col row
        float4 v = *(const float4*)(W + (size_t)r * DH + q * 4);
        uint4 t;
        t.x = f2tf32(0.25f * v.x); t.y = f2tf32(0.25f * v.y);
        t.z = f2tf32(0.25f * v.z); t.w = f2tf32(0.25f * v.w);
        *(uint4*)(Bs + r * BS_STRIDE + q * 4) = t;
    }
    __syncthreads();

    int lane = tid & 31;
    int g  = lane >> 2;        // 0..7
    int tg = lane & 3;         // 0..3
    int w  = tid >> 5;
    int wm = (w >> 1) * 32;    // warp M offset
    int wn = (w & 1) * 32;     // warp N offset

    float c[2][4][4];
    #pragma unroll
    for (int mt = 0; mt < 2; mt++)
        #pragma unroll
        for (int nt = 0; nt < 4; nt++)
            #pragma unroll
            for (int i = 0; i < 4; i++) c[mt][nt][i] = 0.f;

    #pragma unroll
    for (int ks = 0; ks < 16; ks++) {
        int k0 = ks * 8;
        uint32_t a[2][4], b[4][2];
        #pragma unroll
        for (int mt = 0; mt < 2; mt++) {
            const float* ap = As + (wm + mt * 16 + g) * AS_STRIDE + k0 + tg;
            a[mt][0] = __float_as_uint(ap[0]);
            a[mt][1] = __float_as_uint(ap[8 * AS_STRIDE]);
            a[mt][2] = __float_as_uint(ap[4]);
            a[mt][3] = __float_as_uint(ap[8 * AS_STRIDE + 4]);
        }
        #pragma unroll
        for (int nt = 0; nt < 4; nt++) {
            const float* bp = Bs + (k0 + tg) * BS_STRIDE + wn + nt * 8 + g;
            b[nt][0] = __float_as_uint(bp[0]);
            b[nt][1] = __float_as_uint(bp[4 * BS_STRIDE]);
        }
        #pragma unroll
        for (int mt = 0; mt < 2; mt++)
            #pragma unroll
            for (int nt = 0; nt < 4; nt++)
                asm volatile(
                    "mma.sync.aligned.m16n8k8.row.col.f32.tf32.tf32.f32 "
                    "{%0,%1,%2,%3}, {%4,%5,%6,%7}, {%8,%9}, {%0,%1,%2,%3};"
                    : "+f"(c[mt][nt][0]), "+f"(c[mt][nt][1]),
                      "+f"(c[mt][nt][2]), "+f"(c[mt][nt][3])
                    : "r"(a[mt][0]), "r"(a[mt][1]), "r"(a[mt][2]), "r"(a[mt][3]),
                      "r"(b[nt][0]), "r"(b[nt][1]));
    }

    // epilogue: c0,c1 -> (row, tg*2); c2,c3 -> (row+8, tg*2)
    #pragma unroll
    for (int mt = 0; mt < 2; mt++) {
        int row = row0 + wm + mt * 16 + g;
        #pragma unroll
        for (int nt = 0; nt < 4; nt++) {
            int col = wn + nt * 8 + tg * 2;
            if (row < n)
                *(float2*)(y0 + (size_t)row * DH + col) =
                    make_float2(c[mt][nt][0], c[mt][nt][1]);
            if (row + 8 < n)
                *(float2*)(y0 + (size_t)(row + 8) * DH + col) =
                    make_float2(c[mt][nt][2], c[mt][nt][3]);
        }
    }
}

// scan block partials (one block)
__global__ void k_scanpart(int nb, int n, int e) {
    __shared__ int s[NBMAX];
    int t = threadIdx.x;
    int v = (t < nb) ? g_partial[t] : 0;
    s[t] = v;
    __syncthreads();
    for (int o = 1; o < NBMAX; o <<= 1) {
        int u = 0;
        if (t >= o) u = s[t - o];
        __syncthreads();
        if (t >= o) s[t] += u;
        __syncthreads();
    }
    if (t < nb) g_partofs[t] = s[t] - v;
    if (t == 0) g_rowstart[n] = e;
}

// per-block exclusive rescan -> rowstart/cursor
__global__ void k_rowstart(int n) {
    __shared__ int s[256];
    int t = threadIdx.x;
    int i = blockIdx.x * 256 + t;
    int v = (i < n) ? g_deg[i] : 0;
    s[t] = v;
    __syncthreads();
    for (int o = 1; o < 256; o <<= 1) {
        int u = 0;
        if (t >= o) u = s[t - o];
        __syncthreads();
        if (t >= o) s[t] += u;
        __syncthreads();
    }
    if (i < n) {
        int r = g_partofs[blockIdx.x] + s[t] - v;
        g_rowstart[i] = r;
        g_cursor[i]   = r;
    }
}

__global__ void k_fill(const void* __restrict__ eiv, int e) {
    int i = blockIdx.x * blockDim.x + threadIdx.x;
    if (i >= e) return;
    int s, d;
    if (g_is64) {
        s = (int)((const long long*)eiv)[i];
        d = (int)((const long long*)eiv)[(size_t)e + i];
    } else {
        s = ((const int*)eiv)[i];
        d = ((const int*)eiv)[(size_t)e + i];
    }
    int p = atomicAdd(&g_cursor[d], 1);
    g_edge[p] = make_int2(s, __float_as_int(g_dis[s] * g_dis[d]));
}

// One warp per node in d=64; each lane owns 2 features (float2).
// 8 gathers in flight. LAST=1 fuses: out = y0 + y1 + yin + acc + b.
template <int LAST>
__global__ void k_layer(const float* __restrict__ yin,
                        float* __restrict__ yout,
                        const float* __restrict__ y0,
                        const float* __restrict__ y1,
                        const float* __restrict__ bvec,
                        float* __restrict__ out, int n) {
    int gw = (blockIdx.x * blockDim.x + threadIdx.x) >> 5;
    if (gw >= n) return;
    int lane = threadIdx.x & 31;

    int beg = g_rowstart[gw];
    int end = g_rowstart[gw + 1];
    int last = end - 1;

    float accx = 0.f, accy = 0.f;
    for (int e = beg; e < end; e += 8) {
        int2  p[8];
        float w[8];
        #pragma unroll
        for (int j = 0; j < 8; j++) {
            p[j] = g_edge[min(e + j, last)];
            w[j] = (e + j <= last) ? __int_as_float(p[j].y) : 0.f;
        }
        float2 v[8];
        #pragma unroll
        for (int j = 0; j < 8; j++)
            v[j] = *(const float2*)(yin + (size_t)p[j].x * DH + lane * 2);
        #pragma unroll
        for (int j = 0; j < 8; j++) {
            accx += w[j] * v[j].x;
            accy += w[j] * v[j].y;
        }
    }

    size_t off = (size_t)gw * DH + lane * 2;
    if (LAST) {
        float2 a = *(const float2*)(y0 + off);
        float2 b = *(const float2*)(y1 + off);
        float2 c = *(const float2*)(yin + off);
        float2 bb = *(const float2*)(bvec + lane * 2);
        float2 o = make_float2(a.x + b.x + c.x + accx + bb.x,
                               a.y + b.y + c.y + accy + bb.y);
        *(float2*)(out + off) = o;
    } else {
        *(float2*)(yout + off) = make_float2(accx, accy);
    }
}

// ---------------------------------------------------------------------------

extern "C" void kernel_launch(void* const* d_in, const int* in_sizes, int n_in,
                              void* d_out, int out_size) {
    const float* x  = (const float*)d_in[0];   // [N,128]
    const float* W  = (const float*)d_in[1];   // [128,64]
    const float* b  = (const float*)d_in[2];   // [64]
    const void*  ei = d_in[3];                 // [2,E]
    float* out = (float*)d_out;

    int n = in_sizes[0] / DFEAT;
    int e = in_sizes[3] / 2;

    float *y0, *y1, *y2;
    cudaGetSymbolAddress((void**)&y0, g_y0);
    cudaGetSymbolAddress((void**)&y1, g_y1);
    cudaGetSymbolAddress((void**)&y2, g_y2);

    cudaFuncSetAttribute(k_gemm_y,
                         cudaFuncAttributeMaxDynamicSharedMemorySize, GEMM_SMEM);

    const int TB = 256;
    int nb_n = (n + TB - 1) / TB;
    int nb_e = (e + TB - 1) / TB;

    k_init<<<nb_n, TB>>>((const long long*)ei, n);               // 1
    k_deg<<<nb_e, TB>>>(ei, e);                                  // 2
    k_blocksum<<<nb_n, TB>>>(n);                                 // 3
    k_gemm_y<<<(n + 127) / 128, 256, GEMM_SMEM>>>(x, W, y0, n);  // 4 (ncu)
    k_scanpart<<<1, NBMAX>>>(nb_n, n, e);                        // 5
    k_rowstart<<<nb_n, TB>>>(n);                                 // 6
    k_fill<<<nb_e, TB>>>(ei, e);                                 // 7

    int lg = (n * 32 + TB - 1) / TB;
    k_layer<0><<<lg, TB>>>(y0, y1, nullptr, nullptr, nullptr, nullptr, n); // 8
    k_layer<0><<<lg, TB>>>(y1, y2, nullptr, nullptr, nullptr, nullptr, n); // 9
    k_layer<1><<<lg, TB>>>(y2, nullptr, y0, y1, b, out, n);                // 10
}

// round 7
// speedup vs baseline: 1.1980x; 1.0228x over previous
#include <cuda_runtime.h>
#include <cstdint>

// ---------------------------------------------------------------------------
// LightGCN encoder. Identity: propagation S is linear over features and W
// acts on the feature dim, so  mean_k(S^k x) @ W = mean_k(S^k (x @ W)).
// Pipeline (fork-join graph):
//   branch A (side stream): y0 = x @ (0.25*W)  [tf32 tensor-core mma]
//   branch B (main stream): CSR build (deg -> dis -> scan -> fill)
//   join, then: y1 = S y0, y2 = S y1, out = y0+y1+y2+S y2 + b
// g_deg is re-zeroed by its last reader (k_rowstart) so no zeroing pass is
// needed (device globals start zeroed; each full replay restores invariant).
// ---------------------------------------------------------------------------

#define NMAX 100000
#define EMAX 625024
#define DFEAT 128
#define DH 64
#define NBMAX 512   // >= ceil(NMAX/256)

#define AS_STRIDE 132
#define BS_STRIDE 72
#define GEMM_SMEM ((128 * AS_STRIDE + 128 * BS_STRIDE) * 4)

__device__ int   g_is64;
__device__ int   g_deg[NMAX];        // zero at entry; re-zeroed by k_rowstart
__device__ float g_dis[NMAX];
__device__ int   g_partial[NBMAX];
__device__ int   g_partofs[NBMAX];
__device__ int   g_rowstart[NMAX + 1];
__device__ int   g_cursor[NMAX];
__device__ int2  g_edge[EMAX];       // {src, bitcast(weight)}
__device__ __align__(16) float g_y0[(size_t)NMAX * DH];
__device__ __align__(16) float g_y1[(size_t)NMAX * DH];
__device__ __align__(16) float g_y2[(size_t)NMAX * DH];

// ---------------------------------------------------------------------------
// dtype probe only (1 block). Reads 256 int64 (2 KB) — in-bounds either way.
__global__ void k_probe(const long long* __restrict__ ei, int n) {
    long long v = ei[threadIdx.x];
    int bad = (v < 0 || v >= (long long)n) ? 1 : 0;
    int any = __syncthreads_or(bad);
    if (threadIdx.x == 0) g_is64 = !any;
}

__global__ void k_deg(const void* __restrict__ eiv, int e) {
    int i = blockIdx.x * blockDim.x + threadIdx.x;
    if (i >= e) return;
    int d;
    if (g_is64) d = (int)((const long long*)eiv)[(size_t)e + i];
    else        d = ((const int*)eiv)[(size_t)e + i];
    atomicAdd(&g_deg[d], 1);
}

// block partial sums of deg (+ dis on the way)
__global__ void k_blocksum(int n) {
    __shared__ int s[256];
    int t = threadIdx.x;
    int i = blockIdx.x * 256 + t;
    int v = (i < n) ? g_deg[i] : 0;
    if (i < n) g_dis[i] = (v > 0) ? rsqrtf((float)v) : 0.0f;
    s[t] = v;
    __syncthreads();
    for (int o = 128; o > 0; o >>= 1) {
        if (t < o) s[t] += s[t + o];
        __syncthreads();
    }
    if (t == 0) g_partial[blockIdx.x] = s[0];
}

__device__ __forceinline__ uint32_t f2tf32(float f) {
    uint32_t u;
    asm("cvt.rna.tf32.f32 %0, %1;" : "=r"(u) : "f"(f));
    return u;
}

// y0 = x @ (0.25*W) via tf32 mma.sync. BM=128, BN=64, full K=128 in smem.
__global__ void k_gemm_y(const float* __restrict__ x,
                         const float* __restrict__ W,
                         float* __restrict__ y0, int n) {
    extern __shared__ float sm[];
    float* As = sm;                      // [128][AS_STRIDE]
    float* Bs = sm + 128 * AS_STRIDE;    // [128][BS_STRIDE]

    int tid = threadIdx.x;
    int row0 = blockIdx.x * 128;

    #pragma unroll
    for (int j = 0; j < 16; j++) {
        int idx = tid + j * 256;
        int r = idx >> 5;
        int q = idx & 31;
        float4 v = make_float4(0.f, 0.f, 0.f, 0.f);
        int row = row0 + r;
        if (row < n) v = *(const float4*)(x + (size_t)row * DFEAT + q * 4);
        uint4 t;
        t.x = f2tf32(v.x); t.y = f2tf32(v.y);
        t.z = f2tf32(v.z); t.w = f2tf32(v.w);
        *(uint4*)(As + r * AS_STRIDE + q * 4) = t;
    }
    #pragma unroll
    for (int j = 0; j < 8; j++) {
        int idx = tid + j * 256;
        int r = idx >> 4;
        int q = idx & 15;
        float4 v = *(const float4*)(W + (size_t)r * DH + q * 4);
        uint4 t;
        t.x = f2tf32(0.25f * v.x); t.y = f2tf32(0.25f * v.y);
        t.z = f2tf32(0.25f * v.z); t.w = f2tf32(0.25f * v.w);
        *(uint4*)(Bs + r * BS_STRIDE + q * 4) = t;
    }
    __syncthreads();

    int lane = tid & 31;
    int g  = lane >> 2;
    int tg = lane & 3;
    int w  = tid >> 5;
    int wm = (w >> 1) * 32;
    int wn = (w & 1) * 32;

    float c[2][4][4];
    #pragma unroll
    for (int mt = 0; mt < 2; mt++)
        #pragma unroll
        for (int nt = 0; nt < 4; nt++)
            #pragma unroll
            for (int i = 0; i < 4; i++) c[mt][nt][i] = 0.f;

    #pragma unroll
    for (int ks = 0; ks < 16; ks++) {
        int k0 = ks * 8;
        uint32_t a[2][4], b[4][2];
        #pragma unroll
        for (int mt = 0; mt < 2; mt++) {
            const float* ap = As + (wm + mt * 16 + g) * AS_STRIDE + k0 + tg;
            a[mt][0] = __float_as_uint(ap[0]);
            a[mt][1] = __float_as_uint(ap[8 * AS_STRIDE]);
            a[mt][2] = __float_as_uint(ap[4]);
            a[mt][3] = __float_as_uint(ap[8 * AS_STRIDE + 4]);
        }
        #pragma unroll
        for (int nt = 0; nt < 4; nt++) {
            const float* bp = Bs + (k0 + tg) * BS_STRIDE + wn + nt * 8 + g;
            b[nt][0] = __float_as_uint(bp[0]);
            b[nt][1] = __float_as_uint(bp[4 * BS_STRIDE]);
        }
        #pragma unroll
        for (int mt = 0; mt < 2; mt++)
            #pragma unroll
            for (int nt = 0; nt < 4; nt++)
                asm volatile(
                    "mma.sync.aligned.m16n8k8.row.col.f32.tf32.tf32.f32 "
                    "{%0,%1,%2,%3}, {%4,%5,%6,%7}, {%8,%9}, {%0,%1,%2,%3};"
                    : "+f"(c[mt][nt][0]), "+f"(c[mt][nt][1]),
                      "+f"(c[mt][nt][2]), "+f"(c[mt][nt][3])
                    : "r"(a[mt][0]), "r"(a[mt][1]), "r"(a[mt][2]), "r"(a[mt][3]),
                      "r"(b[nt][0]), "r"(b[nt][1]));
    }

    #pragma unroll
    for (int mt = 0; mt < 2; mt++) {
        int row = row0 + wm + mt * 16 + g;
        #pragma unroll
        for (int nt = 0; nt < 4; nt++) {
            int col = wn + nt * 8 + tg * 2;
            if (row < n)
                *(float2*)(y0 + (size_t)row * DH + col) =
                    make_float2(c[mt][nt][0], c[mt][nt][1]);
            if (row + 8 < n)
                *(float2*)(y0 + (size_t)(row + 8) * DH + col) =
                    make_float2(c[mt][nt][2], c[mt][nt][3]);
        }
    }
}

// scan block partials (one block)
__global__ void k_scanpart(int nb, int n, int e) {
    __shared__ int s[NBMAX];
    int t = threadIdx.x;
    int v = (t < nb) ? g_partial[t] : 0;
    s[t] = v;
    __syncthreads();
    for (int o = 1; o < NBMAX; o <<= 1) {
        int u = 0;
        if (t >= o) u = s[t - o];
        __syncthreads();
        if (t >= o) s[t] += u;
        __syncthreads();
    }
    if (t < nb) g_partofs[t] = s[t] - v;
    if (t == 0) g_rowstart[n] = e;
}

// per-block exclusive rescan -> rowstart/cursor; re-zeroes g_deg (last reader)
__global__ void k_rowstart(int n) {
    __shared__ int s[256];
    int t = threadIdx.x;
    int i = blockIdx.x * 256 + t;
    int v = (i < n) ? g_deg[i] : 0;
    s[t] = v;
    __syncthreads();
    for (int o = 1; o < 256; o <<= 1) {
        int u = 0;
        if (t >= o) u = s[t - o];
        __syncthreads();
        if (t >= o) s[t] += u;
        __syncthreads();
    }
    if (i < n) {
        int r = g_partofs[blockIdx.x] + s[t] - v;
        g_rowstart[i] = r;
        g_cursor[i]   = r;
        g_deg[i]      = 0;     // restore invariant for next replay
    }
}

__global__ void k_fill(const void* __restrict__ eiv, int e) {
    int i = blockIdx.x * blockDim.x + threadIdx.x;
    if (i >= e) return;
    int s, d;
    if (g_is64) {
        s = (int)((const long long*)eiv)[i];
        d = (int)((const long long*)eiv)[(size_t)e + i];
    } else {
        s = ((const int*)eiv)[i];
        d = ((const int*)eiv)[(size_t)e + i];
    }
    int p = atomicAdd(&g_cursor[d], 1);
    g_edge[p] = make_int2(s, __float_as_int(g_dis[s] * g_dis[d]));
}

// One warp per node in d=64; each lane owns 2 features (float2).
// 8 gathers in flight. LAST=1 fuses: out = y0 + y1 + yin + acc + b.
template <int LAST>
__global__ void k_layer(const float* __restrict__ yin,
                        float* __restrict__ yout,
                        const float* __restrict__ y0,
                        const float* __restrict__ y1,
                        const float* __restrict__ bvec,
                        float* __restrict__ out, int n) {
    int gw = (blockIdx.x * blockDim.x + threadIdx.x) >> 5;
    if (gw >= n) return;
    int lane = threadIdx.x & 31;

    int beg = g_rowstart[gw];
    int end = g_rowstart[gw + 1];
    int last = end - 1;

    float accx = 0.f, accy = 0.f;
    for (int e = beg; e < end; e += 8) {
        int2  p[8];
        float w[8];
        #pragma unroll
        for (int j = 0; j < 8; j++) {
            p[j] = g_edge[min(e + j, last)];
            w[j] = (e + j <= last) ? __int_as_float(p[j].y) : 0.f;
        }
        float2 v[8];
        #pragma unroll
        for (int j = 0; j < 8; j++)
            v[j] = *(const float2*)(yin + (size_t)p[j].x * DH + lane * 2);
        #pragma unroll
        for (int j = 0; j < 8; j++) {
            accx += w[j] * v[j].x;
            accy += w[j] * v[j].y;
        }
    }

    size_t off = (size_t)gw * DH + lane * 2;
    if (LAST) {
        float2 a = *(const float2*)(y0 + off);
        float2 b = *(const float2*)(y1 + off);
        float2 c = *(const float2*)(yin + off);
        float2 bb = *(const float2*)(bvec + lane * 2);
        float2 o = make_float2(a.x + b.x + c.x + accx + bb.x,
                               a.y + b.y + c.y + accy + bb.y);
        *(float2*)(out + off) = o;
    } else {
        *(float2*)(yout + off) = make_float2(accx, accy);
    }
}

// ---------------------------------------------------------------------------

extern "C" void kernel_launch(void* const* d_in, const int* in_sizes, int n_in,
                              void* d_out, int out_size) {
    const float* x  = (const float*)d_in[0];   // [N,128]
    const float* W  = (const float*)d_in[1];   // [128,64]
    const float* b  = (const float*)d_in[2];   // [64]
    const void*  ei = d_in[3];                 // [2,E]
    float* out = (float*)d_out;

    int n = in_sizes[0] / DFEAT;
    int e = in_sizes[3] / 2;

    float *y0, *y1, *y2;
    cudaGetSymbolAddress((void**)&y0, g_y0);
    cudaGetSymbolAddress((void**)&y1, g_y1);
    cudaGetSymbolAddress((void**)&y2, g_y2);

    // Lazy one-time handles (host-side only; no device memory). Every call
    // records the identical op sequence -> deterministic captured graph.
    static cudaStream_t s_side = nullptr;
    static cudaEvent_t  s_fork = nullptr, s_join = nullptr;
    if (!s_side) {
        cudaStreamCreateWithFlags(&s_side, cudaStreamNonBlocking);
        cudaEventCreateWithFlags(&s_fork, cudaEventDisableTiming);
        cudaEventCreateWithFlags(&s_join, cudaEventDisableTiming);
        cudaFuncSetAttribute(k_gemm_y,
                             cudaFuncAttributeMaxDynamicSharedMemorySize,
                             GEMM_SMEM);
    }

    const int TB = 256;
    int nb_n = (n + TB - 1) / TB;
    int nb_e = (e + TB - 1) / TB;

    // fork: GEMM branch (depends only on x, W)
    cudaEventRecord(s_fork, 0);
    cudaStreamWaitEvent(s_side, s_fork, 0);
    k_gemm_y<<<(n + 127) / 128, 256, GEMM_SMEM, s_side>>>(x, W, y0, n);
    cudaEventRecord(s_join, s_side);

    // main stream: CSR build chain
    k_probe<<<1, 256>>>((const long long*)ei, n);
    k_deg<<<nb_e, TB>>>(ei, e);
    k_blocksum<<<nb_n, TB>>>(n);
    k_scanpart<<<1, NBMAX>>>(nb_n, n, e);
    k_rowstart<<<nb_n, TB>>>(n);
    k_fill<<<nb_e, TB>>>(ei, e);

    // join: layers need both y0 (GEMM) and CSR
    cudaStreamWaitEvent(0, s_join, 0);

    int lg = (n * 32 + TB - 1) / TB;
    k_layer<0><<<lg, TB>>>(y0, y1, nullptr, nullptr, nullptr, nullptr, n);
    k_layer<0><<<lg, TB>>>(y1, y2, nullptr, nullptr, nullptr, nullptr, n);
    k_layer<1><<<lg, TB>>>(y2, nullptr, y0, y1, b, out, n);
}

// round 12
// speedup vs baseline: 1.4958x; 1.2485x over previous
#include <cuda_runtime.h>
#include <cstdint>

// ---------------------------------------------------------------------------
// LightGCN encoder. Identity: propagation S is linear over features and W
// acts on the feature dim, so  mean_k(S^k x) @ W = mean_k(S^k (x @ W)).
// Fork-join graph, 9 launches:
//   side:  k_gemm_y (tf32 mma)                        [needs x, W]
//   main:  k_deg -> k_blocksum -> k_scanpart -> k_rowstart -> k_fill
//   join:  3x k_layer
// Dtype of edge_index (int32/int64) re-derived per block (inline probe).
// g_deg re-zeroed by k_rowstart (its last reader); device globals start 0.
// No cross-block spin anywhere (lookback scan removed after R8 hang).
// ---------------------------------------------------------------------------

#define NMAX 100000
#define EMAX 625024
#define DFEAT 128
#define DH 64
#define NBMAX 512   // >= ceil(NMAX/256)

#define AS_STRIDE 132
#define BS_STRIDE 72
#define GEMM_SMEM ((128 * AS_STRIDE + 128 * BS_STRIDE) * 4)

__device__ int   g_deg[NMAX];        // zero at entry; re-zeroed by k_rowstart
__device__ float g_dis[NMAX];
__device__ int   g_partial[NBMAX];
__device__ int   g_partofs[NBMAX];
__device__ int   g_rowstart[NMAX + 1];
__device__ int   g_cursor[NMAX];
__device__ int2  g_edge[EMAX];       // {src, bitcast(weight)}
__device__ __align__(16) float g_y0[(size_t)NMAX * DH];
__device__ __align__(16) float g_y1[(size_t)NMAX * DH];
__device__ __align__(16) float g_y2[(size_t)NMAX * DH];

// ---------------------------------------------------------------------------
// Inline dtype probe: reads first 64 int64 words (512 B, in-bounds under
// either dtype). Genuine int64 -> all in [0,n); packed int32 pairs give
// values >= 2^32 (unless an odd-slot index is 0: P ~ (1/n)^64, negligible).
__device__ __forceinline__ int probe_is64(const void* eiv, int n) {
    bool bad = false;
    if (threadIdx.x < 64) {
        long long v = ((const long long*)eiv)[threadIdx.x];
        bad = (v < 0 || v >= (long long)n);
    }
    return !__syncthreads_or(bad);
}

// degree histogram
__global__ void k_deg(const void* __restrict__ eiv, int e, int n) {
    int is64 = probe_is64(eiv, n);
    int i = blockIdx.x * blockDim.x + threadIdx.x;
    if (i >= e) return;
    int d;
    if (is64) d = (int)((const long long*)eiv)[(size_t)e + i];
    else      d = ((const int*)eiv)[(size_t)e + i];
    atomicAdd(&g_deg[d], 1);
}

// block partial sums of deg (+ dis on the way)
__global__ void k_blocksum(int n) {
    __shared__ int s[256];
    int t = threadIdx.x;
    int i = blockIdx.x * 256 + t;
    int v = (i < n) ? g_deg[i] : 0;
    if (i < n) g_dis[i] = (v > 0) ? rsqrtf((float)v) : 0.0f;
    s[t] = v;
    __syncthreads();
    for (int o = 128; o > 0; o >>= 1) {
        if (t < o) s[t] += s[t + o];
        __syncthreads();
    }
    if (t == 0) g_partial[blockIdx.x] = s[0];
}

// scan block partials (one block)
__global__ void k_scanpart(int nb, int n, int e) {
    __shared__ int s[NBMAX];
    int t = threadIdx.x;
    int v = (t < nb) ? g_partial[t] : 0;
    s[t] = v;
    __syncthreads();
    for (int o = 1; o < NBMAX; o <<= 1) {
        int u = 0;
        if (t >= o) u = s[t - o];
        __syncthreads();
        if (t >= o) s[t] += u;
        __syncthreads();
    }
    if (t < nb) g_partofs[t] = s[t] - v;
    if (t == 0) g_rowstart[n] = e;
}

// per-block exclusive rescan -> rowstart/cursor; re-zeroes g_deg (last reader)
__global__ void k_rowstart(int n) {
    __shared__ int s[256];
    int t = threadIdx.x;
    int i = blockIdx.x * 256 + t;
    int v = (i < n) ? g_deg[i] : 0;
    s[t] = v;
    __syncthreads();
    for (int o = 1; o < 256; o <<= 1) {
        int u = 0;
        if (t >= o) u = s[t - o];
        __syncthreads();
        if (t >= o) s[t] += u;
        __syncthreads();
    }
    if (i < n) {
        int r = g_partofs[blockIdx.x] + s[t] - v;
        g_rowstart[i] = r;
        g_cursor[i]   = r;
        g_deg[i]      = 0;     // restore invariant for next replay
    }
}

__global__ void k_fill(const void* __restrict__ eiv, int e, int n) {
    int is64 = probe_is64(eiv, n);
    int i = blockIdx.x * blockDim.x + threadIdx.x;
    if (i >= e) return;
    int s, d;
    if (is64) {
        s = (int)((const long long*)eiv)[i];
        d = (int)((const long long*)eiv)[(size_t)e + i];
    } else {
        s = ((const int*)eiv)[i];
        d = ((const int*)eiv)[(size_t)e + i];
    }
    int p = atomicAdd(&g_cursor[d], 1);
    g_edge[p] = make_int2(s, __float_as_int(g_dis[s] * g_dis[d]));
}

__device__ __forceinline__ uint32_t f2tf32(float f) {
    uint32_t u;
    asm("cvt.rna.tf32.f32 %0, %1;" : "=r"(u) : "f"(f));
    return u;
}

// y0 = x @ (0.25*W) via tf32 mma.sync. BM=128, BN=64, full K=128 in smem.
__global__ void k_gemm_y(const float* __restrict__ x,
                         const float* __restrict__ W,
                         float* __restrict__ y0, int n) {
    extern __shared__ float sm[];
    float* As = sm;                      // [128][AS_STRIDE]
    float* Bs = sm + 128 * AS_STRIDE;    // [128][BS_STRIDE]

    int tid = threadIdx.x;
    int row0 = blockIdx.x * 128;

    #pragma unroll
    for (int j = 0; j < 16; j++) {
        int idx = tid + j * 256;
        int r = idx >> 5;
        int q = idx & 31;
        float4 v = make_float4(0.f, 0.f, 0.f, 0.f);
        int row = row0 + r;
        if (row < n) v = *(const float4*)(x + (size_t)row * DFEAT + q * 4);
        uint4 t;
        t.x = f2tf32(v.x); t.y = f2tf32(v.y);
        t.z = f2tf32(v.z); t.w = f2tf32(v.w);
        *(uint4*)(As + r * AS_STRIDE + q * 4) = t;
    }
    #pragma unroll
    for (int j = 0; j < 8; j++) {
        int idx = tid + j * 256;
        int r = idx >> 4;
        int q = idx & 15;
        float4 v = *(const float4*)(W + (size_t)r * DH + q * 4);
        uint4 t;
        t.x = f2tf32(0.25f * v.x); t.y = f2tf32(0.25f * v.y);
        t.z = f2tf32(0.25f * v.z); t.w = f2tf32(0.25f * v.w);
        *(uint4*)(Bs + r * BS_STRIDE + q * 4) = t;
    }
    __syncthreads();

    int lane = tid & 31;
    int g  = lane >> 2;
    int tg = lane & 3;
    int w  = tid >> 5;
    int wm = (w >> 1) * 32;
    int wn = (w & 1) * 32;

    float c[2][4][4];
    #pragma unroll
    for (int mt = 0; mt < 2; mt++)
        #pragma unroll
        for (int nt = 0; nt < 4; nt++)
            #pragma unroll
            for (int i = 0; i < 4; i++) c[mt][nt][i] = 0.f;

    #pragma unroll
    for (int ks = 0; ks < 16; ks++) {
        int k0 = ks * 8;
        uint32_t a[2][4], b[4][2];
        #pragma unroll
        for (int mt = 0; mt < 2; mt++) {
            const float* ap = As + (wm + mt * 16 + g) * AS_STRIDE + k0 + tg;
            a[mt][0] = __float_as_uint(ap[0]);
            a[mt][1] = __float_as_uint(ap[8 * AS_STRIDE]);
            a[mt][2] = __float_as_uint(ap[4]);
            a[mt][3] = __float_as_uint(ap[8 * AS_STRIDE + 4]);
        }
        #pragma unroll
        for (int nt = 0; nt < 4; nt++) {
            const float* bp = Bs + (k0 + tg) * BS_STRIDE + wn + nt * 8 + g;
            b[nt][0] = __float_as_uint(bp[0]);
            b[nt][1] = __float_as_uint(bp[4 * BS_STRIDE]);
        }
        #pragma unroll
        for (int mt = 0; mt < 2; mt++)
            #pragma unroll
            for (int nt = 0; nt < 4; nt++)
                asm volatile(
                    "mma.sync.aligned.m16n8k8.row.col.f32.tf32.tf32.f32 "
                    "{%0,%1,%2,%3}, {%4,%5,%6,%7}, {%8,%9}, {%0,%1,%2,%3};"
                    : "+f"(c[mt][nt][0]), "+f"(c[mt][nt][1]),
                      "+f"(c[mt][nt][2]), "+f"(c[mt][nt][3])
                    : "r"(a[mt][0]), "r"(a[mt][1]), "r"(a[mt][2]), "r"(a[mt][3]),
                      "r"(b[nt][0]), "r"(b[nt][1]));
    }

    #pragma unroll
    for (int mt = 0; mt < 2; mt++) {
        int row = row0 + wm + mt * 16 + g;
        #pragma unroll
        for (int nt = 0; nt < 4; nt++) {
            int col = wn + nt * 8 + tg * 2;
            if (row < n)
                *(float2*)(y0 + (size_t)row * DH + col) =
                    make_float2(c[mt][nt][0], c[mt][nt][1]);
            if (row + 8 < n)
                *(float2*)(y0 + (size_t)(row + 8) * DH + col) =
                    make_float2(c[mt][nt][2], c[mt][nt][3]);
        }
    }
}

// Two nodes per warp: 16 lanes x float4 each (d=64). Exact predicated
// bounds (no wasted gathers), 4 gathers in flight per half-warp.
// LAST=1 fuses: out = y0 + y1 + yin + acc + b.
template <int LAST>
__global__ void k_layer(const float* __restrict__ yin,
                        float* __restrict__ yout,
                        const float* __restrict__ y0,
                        const float* __restrict__ y1,
                        const float* __restrict__ bvec,
                        float* __restrict__ out, int n) {
    int gw = (blockIdx.x * blockDim.x + threadIdx.x) >> 5;
    int lane = threadIdx.x & 31;
    int half = lane >> 4;
    int sub  = lane & 15;
    int node = gw * 2 + half;
    if (node >= n) return;

    int beg = g_rowstart[node];
    int end = g_rowstart[node + 1];

    float4 acc = make_float4(0.f, 0.f, 0.f, 0.f);
    for (int e = beg; e < end; e += 4) {
        #pragma unroll
        for (int j = 0; j < 4; j++) {
            int idx = e + j;
            if (idx < end) {
                int2 p = g_edge[idx];
                float w = __int_as_float(p.y);
                float4 v = *((const float4*)(yin + (size_t)p.x * DH) + sub);
                acc.x += w * v.x;
                acc.y += w * v.y;
                acc.z += w * v.z;
                acc.w += w * v.w;
            }
        }
    }

    size_t off = (size_t)node * DH + sub * 4;
    if (LAST) {
        float4 a = *(const float4*)(y0 + off);
        float4 c = *(const float4*)(y1 + off);
        float4 d = *(const float4*)(yin + off);
        float4 bb = *(const float4*)(bvec + sub * 4);
        *(float4*)(out + off) = make_float4(
            a.x + c.x + d.x + acc.x + bb.x,
            a.y + c.y + d.y + acc.y + bb.y,
            a.z + c.z + d.z + acc.z + bb.z,
            a.w + c.w + d.w + acc.w + bb.w);
    } else {
        *(float4*)(yout + off) = acc;
    }
}

// ---------------------------------------------------------------------------

extern "C" void kernel_launch(void* const* d_in, const int* in_sizes, int n_in,
                              void* d_out, int out_size) {
    const float* x  = (const float*)d_in[0];   // [N,128]
    const float* W  = (const float*)d_in[1];   // [128,64]
    const float* b  = (const float*)d_in[2];   // [64]
    const void*  ei = d_in[3];                 // [2,E]
    float* out = (float*)d_out;

    int n = in_sizes[0] / DFEAT;
    int e = in_sizes[3] / 2;

    float *y0, *y1, *y2;
    cudaGetSymbolAddress((void**)&y0, g_y0);
    cudaGetSymbolAddress((void**)&y1, g_y1);
    cudaGetSymbolAddress((void**)&y2, g_y2);

    static cudaStream_t s_side = nullptr;
    static cudaEvent_t  s_fork = nullptr, s_join = nullptr;
    if (!s_side) {
        cudaStreamCreateWithFlags(&s_side, cudaStreamNonBlocking);
        cudaEventCreateWithFlags(&s_fork, cudaEventDisableTiming);
        cudaEventCreateWithFlags(&s_join, cudaEventDisableTiming);
        cudaFuncSetAttribute(k_gemm_y,
                             cudaFuncAttributeMaxDynamicSharedMemorySize,
                             GEMM_SMEM);
    }

    const int TB = 256;
    int nb_n = (n + TB - 1) / TB;
    int nb_e = (e + TB - 1) / TB;

    // fork: GEMM branch (depends only on x, W)
    cudaEventRecord(s_fork, 0);
    cudaStreamWaitEvent(s_side, s_fork, 0);
    k_gemm_y<<<(n + 127) / 128, 256, GEMM_SMEM, s_side>>>(x, W, y0, n);
    cudaEventRecord(s_join, s_side);

    // main stream: CSR build chain
    k_deg<<<nb_e, TB>>>(ei, e, n);
    k_blocksum<<<nb_n, TB>>>(n);
    k_scanpart<<<1, NBMAX>>>(nb_n, n, e);
    k_rowstart<<<nb_n, TB>>>(n);
    k_fill<<<nb_e, TB>>>(ei, e, n);

    // join: layers need both y0 (GEMM) and CSR
    cudaStreamWaitEvent(0, s_join, 0);

    int lg = (n * 16 + TB - 1) / TB;   // 2 nodes per warp
    k_layer<0><<<lg, TB>>>(y0, y1, nullptr, nullptr, nullptr, nullptr, n);
    k_layer<0><<<lg, TB>>>(y1, y2, nullptr, nullptr, nullptr, nullptr, n);
    k_layer<1><<<lg, TB>>>(y2, nullptr, y0, y1, b, out, n);
}